// round 10
// baseline (speedup 1.0000x reference)
#include <cuda_runtime.h>
#include <cuda_bf16.h>
#include <cstdint>

#define D 128
#define MAX_DST 65536

// ---- scratch (__device__ globals per allocation rules) ----
__device__ int   g_off[MAX_DST + 1];
__device__ __align__(16) __nv_bfloat16 g_Wt_hi[2 * 128 * 128]; // [src][n][k] transposed hi
__device__ __align__(16) __nv_bfloat16 g_Wt_lo[2 * 128 * 128]; // [src][n][k] transposed lo
__device__ float g_bsum[128];

// ============================================================
// Kernel 0: CSR offsets from SORTED dst (no atomics) + W prep fused
// ============================================================
__global__ void prep_kernel(const int* __restrict__ dst, int n_edges, int n_dst,
                            const float* __restrict__ Wself, const float* __restrict__ Wneigh,
                            const float* __restrict__ bself, const float* __restrict__ bneigh,
                            int offBlocks) {
    if ((int)blockIdx.x >= offBlocks) {
        int t = (blockIdx.x - offBlocks) * blockDim.x + threadIdx.x;  // 0..4095
        for (int o = t; o < 2 * 128 * 128; o += 16 * 256) {
            int s = o >> 14, rem = o & 16383;
            int n = rem >> 7, k = rem & 127;
            const float* W = s ? Wneigh : Wself;
            float x = W[k * 128 + n];
            __nv_bfloat16 h = __float2bfloat16(x);
            g_Wt_hi[o] = h;
            g_Wt_lo[o] = __float2bfloat16(x - __bfloat162float(h));
        }
        if ((int)blockIdx.x == offBlocks && threadIdx.x < 128)
            g_bsum[threadIdx.x] = bself[threadIdx.x] + bneigh[threadIdx.x];
        return;
    }
    int e = blockIdx.x * blockDim.x + threadIdx.x;
    if (e > n_edges) return;
    if (e == 0) {
        int d1 = dst[0];
        for (int d = 0; d <= d1; ++d) g_off[d] = 0;
    } else if (e == n_edges) {
        int d0 = dst[n_edges - 1];
        for (int d = d0 + 1; d <= n_dst; ++d) g_off[d] = n_edges;
    } else {
        int d0 = dst[e - 1];
        int d1 = dst[e];
        for (int d = d0 + 1; d <= d1; ++d) g_off[d] = e;
    }
}

// ============================================================
// Kernel 1 (fused): gather-aggregate + HMMA bf16-split GEMM
//   out = [feat[:n_dst] | mean-neigh] @ [W_self ; W_neigh] + (b_self+b_neigh)
//   CTA tile 128x128, 8 warps (4m x 2n), warp tile 32x64.
//   8 phases of K=32: s=0 -> A from feat rows; s=1 -> A gathered+meaned
//   inline from feat via CSR (4 threads/row, 8 k each, 2-edge unroll).
//   3 HMMA products per (m16,n8,k16): hihi, hilo, lohi.
// ============================================================
#define AST 40                     // smem row stride in bf16 (80 B)
#define S_BIAS 0
#define S_A_HI 512
#define S_A_LO (512 + 10240)
#define S_W_HI (512 + 20480)
#define S_W_LO (512 + 30720)
#define S_TOTAL (512 + 40960)      // 41472 B static smem

__device__ __forceinline__ uint32_t pack_bf16_hi(float a, float b, uint32_t& lo_out) {
    __nv_bfloat16 ha = __float2bfloat16(a);
    __nv_bfloat16 hb = __float2bfloat16(b);
    __nv_bfloat16 la = __float2bfloat16(a - __bfloat162float(ha));
    __nv_bfloat16 lb = __float2bfloat16(b - __bfloat162float(hb));
    lo_out = (uint32_t)__bfloat16_as_ushort(la) | ((uint32_t)__bfloat16_as_ushort(lb) << 16);
    return (uint32_t)__bfloat16_as_ushort(ha) | ((uint32_t)__bfloat16_as_ushort(hb) << 16);
}

__device__ __forceinline__ void mma16816(float* c, const uint32_t* a, const uint32_t* b) {
    asm volatile(
        "mma.sync.aligned.m16n8k16.row.col.f32.bf16.bf16.f32 "
        "{%0,%1,%2,%3}, {%4,%5,%6,%7}, {%8,%9}, {%0,%1,%2,%3};"
        : "+f"(c[0]), "+f"(c[1]), "+f"(c[2]), "+f"(c[3])
        : "r"(a[0]), "r"(a[1]), "r"(a[2]), "r"(a[3]), "r"(b[0]), "r"(b[1]));
}

__global__ __launch_bounds__(256) void gemm_fused_kernel(
    const float* __restrict__ feat, const int* __restrict__ src,
    float* __restrict__ out) {

    __shared__ __align__(16) char smem[S_TOTAL];

    const int tid  = threadIdx.x;
    const int wid  = tid >> 5;
    const int lane = tid & 31;
    const int wm   = wid >> 1;        // 0..3 -> m rows [wm*32, +32)
    const int wn   = wid & 1;         // 0..1 -> n cols [wn*64, +64)
    const int rowBase = blockIdx.x * 128;

    if (tid < 128) ((float*)(smem + S_BIAS))[tid] = g_bsum[tid];

    float acc[2][8][4];
#pragma unroll
    for (int mt = 0; mt < 2; ++mt)
#pragma unroll
        for (int nt = 0; nt < 8; ++nt)
#pragma unroll
            for (int q = 0; q < 4; ++q) acc[mt][nt][q] = 0.f;

    const int lrow = lane >> 2;       // 0..7
    const int lkp  = lane & 3;        // 0..3 -> k pair (lkp*2)

    for (int ph = 0; ph < 8; ++ph) {
        const int s = ph >> 2;                // 0 = self (feat rows), 1 = neighbor gather
        const int kbase = (ph & 3) * 32;

        __syncthreads();   // previous phase's compute done with SMEM

        if (s == 0) {
            // ---- stage A: 128 rows x 32 k from feat, fp32 -> bf16 hi/lo ----
#pragma unroll
            for (int i = 0; i < 2; ++i) {
                int c = tid + i * 256;            // 512 chunks of 8 k
                int r = c >> 2, kc = c & 3;
                const float4* p = (const float4*)(feat + (size_t)(rowBase + r) * D + kbase + kc * 8);
                float4 x0 = p[0], x1 = p[1];
                uint32_t h0, h1, h2, h3, l0, l1, l2, l3;
                h0 = pack_bf16_hi(x0.x, x0.y, l0);
                h1 = pack_bf16_hi(x0.z, x0.w, l1);
                h2 = pack_bf16_hi(x1.x, x1.y, l2);
                h3 = pack_bf16_hi(x1.z, x1.w, l3);
                uint32_t off = r * (AST * 2) + kc * 16;
                *(uint4*)(smem + S_A_HI + off) = make_uint4(h0, h1, h2, h3);
                *(uint4*)(smem + S_A_LO + off) = make_uint4(l0, l1, l2, l3);
            }
        } else {
            // ---- stage A: gather + mean over CSR edges, k-slice of 32 ----
            const float4* fb = (const float4*)feat;
            const int k4 = (kbase >> 2);          // float4 offset within row
#pragma unroll
            for (int i = 0; i < 2; ++i) {
                int c = tid + i * 256;
                int r = c >> 2, kc = c & 3;
                int row = rowBase + r;
                int lo = g_off[row], hiE = g_off[row + 1];

                float4 s0 = make_float4(0.f, 0.f, 0.f, 0.f);
                float4 s1 = make_float4(0.f, 0.f, 0.f, 0.f);
                int e = lo;
                for (; e + 2 <= hiE; e += 2) {
                    int i0 = src[e], i1 = src[e + 1];
                    const float4* p0 = fb + (size_t)i0 * 32 + k4 + kc * 2;
                    const float4* p1 = fb + (size_t)i1 * 32 + k4 + kc * 2;
                    float4 a0 = p0[0], a1 = p0[1];
                    float4 b0 = p1[0], b1 = p1[1];
                    s0.x += a0.x + b0.x; s0.y += a0.y + b0.y;
                    s0.z += a0.z + b0.z; s0.w += a0.w + b0.w;
                    s1.x += a1.x + b1.x; s1.y += a1.y + b1.y;
                    s1.z += a1.z + b1.z; s1.w += a1.w + b1.w;
                }
                if (e < hiE) {
                    const float4* p0 = fb + (size_t)src[e] * 32 + k4 + kc * 2;
                    float4 a0 = p0[0], a1 = p0[1];
                    s0.x += a0.x; s0.y += a0.y; s0.z += a0.z; s0.w += a0.w;
                    s1.x += a1.x; s1.y += a1.y; s1.z += a1.z; s1.w += a1.w;
                }
                float invd = 1.0f / fmaxf((float)(hiE - lo), 1.0f);
                s0.x *= invd; s0.y *= invd; s0.z *= invd; s0.w *= invd;
                s1.x *= invd; s1.y *= invd; s1.z *= invd; s1.w *= invd;

                uint32_t h0, h1, h2, h3, l0, l1, l2, l3;
                h0 = pack_bf16_hi(s0.x, s0.y, l0);
                h1 = pack_bf16_hi(s0.z, s0.w, l1);
                h2 = pack_bf16_hi(s1.x, s1.y, l2);
                h3 = pack_bf16_hi(s1.z, s1.w, l3);
                uint32_t off = r * (AST * 2) + kc * 16;
                *(uint4*)(smem + S_A_HI + off) = make_uint4(h0, h1, h2, h3);
                *(uint4*)(smem + S_A_LO + off) = make_uint4(l0, l1, l2, l3);
            }
        }

        // ---- stage W: 128 n-rows x 32 k (pre-split bf16) ----
#pragma unroll
        for (int i = 0; i < 2; ++i) {
            int c = tid + i * 256;
            int n = c >> 2, kc = c & 3;
            size_t go = ((size_t)(s * 128 + n)) * 128 + kbase + kc * 8;
            uint4 wh = *(const uint4*)(g_Wt_hi + go);
            uint4 wl = *(const uint4*)(g_Wt_lo + go);
            uint32_t off = n * (AST * 2) + kc * 16;
            *(uint4*)(smem + S_W_HI + off) = wh;
            *(uint4*)(smem + S_W_LO + off) = wl;
        }
        __syncthreads();

        // ---- compute: 2 k16-steps, 3 products each ----
#pragma unroll
        for (int k16 = 0; k16 < 2; ++k16) {
            const uint32_t kb = k16 * 32 + lkp * 4;

            uint32_t a_hi[2][4], a_lo[2][4];
#pragma unroll
            for (int mt = 0; mt < 2; ++mt) {
                uint32_t rb = (wm * 32 + mt * 16 + lrow) * (AST * 2) + kb;
                a_hi[mt][0] = *(const uint32_t*)(smem + S_A_HI + rb);
                a_hi[mt][1] = *(const uint32_t*)(smem + S_A_HI + rb + 8 * (AST * 2));
                a_hi[mt][2] = *(const uint32_t*)(smem + S_A_HI + rb + 16);
                a_hi[mt][3] = *(const uint32_t*)(smem + S_A_HI + rb + 8 * (AST * 2) + 16);
                a_lo[mt][0] = *(const uint32_t*)(smem + S_A_LO + rb);
                a_lo[mt][1] = *(const uint32_t*)(smem + S_A_LO + rb + 8 * (AST * 2));
                a_lo[mt][2] = *(const uint32_t*)(smem + S_A_LO + rb + 16);
                a_lo[mt][3] = *(const uint32_t*)(smem + S_A_LO + rb + 8 * (AST * 2) + 16);
            }

#pragma unroll
            for (int nt = 0; nt < 8; ++nt) {
                uint32_t nb = (wn * 64 + nt * 8 + lrow) * (AST * 2) + kb;
                uint32_t b_hi[2], b_lo[2];
                b_hi[0] = *(const uint32_t*)(smem + S_W_HI + nb);
                b_hi[1] = *(const uint32_t*)(smem + S_W_HI + nb + 16);
                b_lo[0] = *(const uint32_t*)(smem + S_W_LO + nb);
                b_lo[1] = *(const uint32_t*)(smem + S_W_LO + nb + 16);
#pragma unroll
                for (int mt = 0; mt < 2; ++mt) {
                    mma16816(acc[mt][nt], a_hi[mt], b_hi);
                    mma16816(acc[mt][nt], a_hi[mt], b_lo);
                    mma16816(acc[mt][nt], a_lo[mt], b_hi);
                }
            }
        }
    }

    // ---- epilogue: bias + store ----
    const float* bias = (const float*)(smem + S_BIAS);
#pragma unroll
    for (int mt = 0; mt < 2; ++mt) {
        int r0 = rowBase + wm * 32 + mt * 16 + lrow;
#pragma unroll
        for (int nt = 0; nt < 8; ++nt) {
            int col = wn * 64 + nt * 8 + lkp * 2;
            float b0 = bias[col], b1 = bias[col + 1];
            float2 v0 = make_float2(acc[mt][nt][0] + b0, acc[mt][nt][1] + b1);
            float2 v1 = make_float2(acc[mt][nt][2] + b0, acc[mt][nt][3] + b1);
            *(float2*)(out + (size_t)r0 * D + col)       = v0;
            *(float2*)(out + (size_t)(r0 + 8) * D + col) = v1;
        }
    }
}

// ============================================================
// launch
// ============================================================
extern "C" void kernel_launch(void* const* d_in, const int* in_sizes, int n_in,
                              void* d_out, int out_size) {
    const float* feat   = (const float*)d_in[0];
    const float* Wself  = (const float*)d_in[1];
    const float* bself  = (const float*)d_in[2];
    const float* Wneigh = (const float*)d_in[3];
    const float* bneigh = (const float*)d_in[4];
    const int*   src    = (const int*)d_in[5];
    const int*   dst    = (const int*)d_in[6];

    int n_edges = in_sizes[5];
    int n_dst   = out_size / D;

    // 0) CSR offsets + W bf16 split/transpose + bias sum (fused)
    {
        int threads = 256;
        int offBlocks = (n_edges + 1 + threads - 1) / threads;
        prep_kernel<<<offBlocks + 16, threads>>>(dst, n_edges, n_dst,
                                                 Wself, Wneigh, bself, bneigh, offBlocks);
    }
    // 1) fused gather-aggregate + HMMA GEMM + bias
    {
        int blocks = n_dst / 128;   // 512
        gemm_fused_kernel<<<blocks, 256>>>(feat, src, (float*)d_out);
    }
}

// round 11
// speedup vs baseline: 1.3653x; 1.3653x over previous
#include <cuda_runtime.h>
#include <cuda_bf16.h>
#include <cstdint>

#define D 128
#define MAX_DST 65536

// ---- scratch (__device__ globals per allocation rules) ----
__device__ int   g_off[MAX_DST + 1];
__device__ __align__(16) uint32_t g_hn_hi[(size_t)MAX_DST * 64];  // 16 MB: bf16x2 hi
__device__ __align__(16) uint32_t g_hn_lo[(size_t)MAX_DST * 64];  // 16 MB: bf16x2 lo
__device__ __align__(16) __nv_bfloat16 g_Wt_hi[2 * 128 * 128];    // [src][n][k] hi
__device__ __align__(16) __nv_bfloat16 g_Wt_lo[2 * 128 * 128];    // [src][n][k] lo
__device__ float g_bsum[128];

__device__ __forceinline__ uint32_t pack_bf16_hi(float a, float b, uint32_t& lo_out) {
    __nv_bfloat16 ha = __float2bfloat16(a);
    __nv_bfloat16 hb = __float2bfloat16(b);
    __nv_bfloat16 la = __float2bfloat16(a - __bfloat162float(ha));
    __nv_bfloat16 lb = __float2bfloat16(b - __bfloat162float(hb));
    lo_out = (uint32_t)__bfloat16_as_ushort(la) | ((uint32_t)__bfloat16_as_ushort(lb) << 16);
    return (uint32_t)__bfloat16_as_ushort(ha) | ((uint32_t)__bfloat16_as_ushort(hb) << 16);
}

// ============================================================
// Kernel 0: CSR offsets from SORTED dst (no atomics) + W prep fused
// ============================================================
__global__ void prep_kernel(const int* __restrict__ dst, int n_edges, int n_dst,
                            const float* __restrict__ Wself, const float* __restrict__ Wneigh,
                            const float* __restrict__ bself, const float* __restrict__ bneigh,
                            int offBlocks) {
    if ((int)blockIdx.x >= offBlocks) {
        int t = (blockIdx.x - offBlocks) * blockDim.x + threadIdx.x;
        for (int o = t; o < 2 * 128 * 128; o += 16 * 256) {
            int s = o >> 14, rem = o & 16383;
            int n = rem >> 7, k = rem & 127;
            const float* W = s ? Wneigh : Wself;
            float x = W[k * 128 + n];
            __nv_bfloat16 h = __float2bfloat16(x);
            g_Wt_hi[o] = h;
            g_Wt_lo[o] = __float2bfloat16(x - __bfloat162float(h));
        }
        if ((int)blockIdx.x == offBlocks && threadIdx.x < 128)
            g_bsum[threadIdx.x] = bself[threadIdx.x] + bneigh[threadIdx.x];
        return;
    }
    int e = blockIdx.x * blockDim.x + threadIdx.x;
    if (e > n_edges) return;
    if (e == 0) {
        int d1 = dst[0];
        for (int d = 0; d <= d1; ++d) g_off[d] = 0;
    } else if (e == n_edges) {
        int d0 = dst[n_edges - 1];
        for (int d = d0 + 1; d <= n_dst; ++d) g_off[d] = n_edges;
    } else {
        int d0 = dst[e - 1];
        int d1 = dst[e];
        for (int d = d0 + 1; d <= d1; ++d) g_off[d] = e;
    }
}

// ============================================================
// Kernel 1: segment-mean aggregation. One warp per dst row.
// Output: bf16 hi/lo packed pairs (conversion done here, not in GEMM).
// ============================================================
__global__ void aggregate_kernel(const float* __restrict__ feat,
                                 const int* __restrict__ src,
                                 int n_dst) {
    int warp = (int)((blockIdx.x * blockDim.x + threadIdx.x) >> 5);
    int lane = threadIdx.x & 31;
    if (warp >= n_dst) return;

    int lo = g_off[warp];
    int hi = g_off[warp + 1];

    const float4* __restrict__ fbase = (const float4*)feat;
    float ax = 0.f, ay = 0.f, az = 0.f, aw = 0.f;

    int e = lo;
    for (; e + 4 <= hi; e += 4) {
        int s0 = src[e + 0];
        int s1 = src[e + 1];
        int s2 = src[e + 2];
        int s3 = src[e + 3];
        float4 v0 = fbase[s0 * 32 + lane];
        float4 v1 = fbase[s1 * 32 + lane];
        float4 v2 = fbase[s2 * 32 + lane];
        float4 v3 = fbase[s3 * 32 + lane];
        ax += (v0.x + v1.x) + (v2.x + v3.x);
        ay += (v0.y + v1.y) + (v2.y + v3.y);
        az += (v0.z + v1.z) + (v2.z + v3.z);
        aw += (v0.w + v1.w) + (v2.w + v3.w);
    }
    for (; e < hi; ++e) {
        float4 v = fbase[src[e] * 32 + lane];
        ax += v.x; ay += v.y; az += v.z; aw += v.w;
    }

    float invd = 1.0f / fmaxf((float)(hi - lo), 1.0f);
    ax *= invd; ay *= invd; az *= invd; aw *= invd;

    uint32_t l0, l1;
    uint32_t h0 = pack_bf16_hi(ax, ay, l0);
    uint32_t h1 = pack_bf16_hi(az, aw, l1);
    size_t base = (size_t)warp * 64 + lane * 2;
    *(uint2*)&g_hn_hi[base] = make_uint2(h0, h1);
    *(uint2*)&g_hn_lo[base] = make_uint2(l0, l1);
}

// ============================================================
// Kernel 2: double-buffered, cp.async-pipelined HMMA bf16-split GEMM
//   out = [feat[:n_dst] | hn] @ [W_self ; W_neigh] + bias
//   8 phases of K=32. Stage ph+1 (cp.async for W / neigh-A; reg-prefetch
//   + convert for self-A) overlaps compute of phase ph.
// ============================================================
#define AST2 80                      // smem row stride in bytes
#define AHI 0
#define ALO 10240
#define WHI 20480
#define WLO 30720
#define STG_BYTES 40960
#define S_TOTAL (512 + 2 * STG_BYTES)   // 82432 B dynamic smem

__device__ __forceinline__ void cpa16(void* sdst, const void* gsrc) {
    uint32_t d = (uint32_t)__cvta_generic_to_shared(sdst);
    asm volatile("cp.async.cg.shared.global [%0], [%1], 16;" :: "r"(d), "l"(gsrc));
}

__device__ __forceinline__ void stage_w(char* stg, int s, int kbase, int tid) {
#pragma unroll
    for (int i = 0; i < 2; ++i) {
        int c = tid + i * 256;
        int n = c >> 2, kc = c & 3;
        size_t go = ((size_t)(s * 128 + n)) * 128 + kbase + kc * 8;
        uint32_t off = n * AST2 + kc * 16;
        cpa16(stg + WHI + off, g_Wt_hi + go);
        cpa16(stg + WLO + off, g_Wt_lo + go);
    }
}
__device__ __forceinline__ void stage_a_neigh(char* stg, int rowBase, int kbase, int tid) {
#pragma unroll
    for (int i = 0; i < 2; ++i) {
        int c = tid + i * 256;
        int r = c >> 2, kc = c & 3;
        size_t gi = (size_t)(rowBase + r) * 64 + (kbase >> 1) + kc * 4;
        uint32_t off = r * AST2 + kc * 16;
        cpa16(stg + AHI + off, g_hn_hi + gi);
        cpa16(stg + ALO + off, g_hn_lo + gi);
    }
}
__device__ __forceinline__ void lda_self(const float* feat, int rowBase, int kbase,
                                         int tid, float4* pf) {
#pragma unroll
    for (int i = 0; i < 2; ++i) {
        int c = tid + i * 256;
        int r = c >> 2, kc = c & 3;
        const float4* p = (const float4*)(feat + (size_t)(rowBase + r) * D + kbase + kc * 8);
        pf[i * 2 + 0] = p[0];
        pf[i * 2 + 1] = p[1];
    }
}
__device__ __forceinline__ void sts_self(char* stg, int tid, const float4* pf) {
#pragma unroll
    for (int i = 0; i < 2; ++i) {
        int c = tid + i * 256;
        int r = c >> 2, kc = c & 3;
        float4 x0 = pf[i * 2 + 0], x1 = pf[i * 2 + 1];
        uint32_t h0, h1, h2, h3, l0, l1, l2, l3;
        h0 = pack_bf16_hi(x0.x, x0.y, l0);
        h1 = pack_bf16_hi(x0.z, x0.w, l1);
        h2 = pack_bf16_hi(x1.x, x1.y, l2);
        h3 = pack_bf16_hi(x1.z, x1.w, l3);
        uint32_t off = r * AST2 + kc * 16;
        *(uint4*)(stg + AHI + off) = make_uint4(h0, h1, h2, h3);
        *(uint4*)(stg + ALO + off) = make_uint4(l0, l1, l2, l3);
    }
}

__device__ __forceinline__ void mma16816(float* c, const uint32_t* a, const uint32_t* b) {
    asm volatile(
        "mma.sync.aligned.m16n8k16.row.col.f32.bf16.bf16.f32 "
        "{%0,%1,%2,%3}, {%4,%5,%6,%7}, {%8,%9}, {%0,%1,%2,%3};"
        : "+f"(c[0]), "+f"(c[1]), "+f"(c[2]), "+f"(c[3])
        : "r"(a[0]), "r"(a[1]), "r"(a[2]), "r"(a[3]), "r"(b[0]), "r"(b[1]));
}

extern __shared__ __align__(16) char smem_dyn[];

__global__ __launch_bounds__(256, 2) void gemm_pipe_kernel(
    const float* __restrict__ feat, float* __restrict__ out) {

    char* smem = smem_dyn;
    const int tid  = threadIdx.x;
    const int wid  = tid >> 5;
    const int lane = tid & 31;
    const int wm   = wid >> 1;
    const int wn   = wid & 1;
    const int rowBase = blockIdx.x * 128;

    char* stg0 = smem + 512;
    char* stg1 = smem + 512 + STG_BYTES;

    if (tid < 128) ((float*)smem)[tid] = g_bsum[tid];

    float acc[2][8][4];
#pragma unroll
    for (int mt = 0; mt < 2; ++mt)
#pragma unroll
        for (int nt = 0; nt < 8; ++nt)
#pragma unroll
            for (int q = 0; q < 4; ++q) acc[mt][nt][q] = 0.f;

    const int lrow = lane >> 2;
    const int lkp  = lane & 3;

    float4 pf[4];

    // ---- prologue: stage phase 0 (self, kbase=0) into stg0 ----
    stage_w(stg0, 0, 0, tid);
    asm volatile("cp.async.commit_group;" ::: "memory");
    lda_self(feat, rowBase, 0, tid, pf);
    sts_self(stg0, tid, pf);

    for (int ph = 0; ph < 8; ++ph) {
        asm volatile("cp.async.wait_group 0;" ::: "memory");
        __syncthreads();

        char* cur = (ph & 1) ? stg1 : stg0;
        char* nxt = (ph & 1) ? stg0 : stg1;
        const bool have_next = (ph < 7);
        const bool next_self = (ph + 1) < 4;

        if (have_next) {
            int ns = (ph + 1) >> 2;
            int nk = ((ph + 1) & 3) * 32;
            stage_w(nxt, ns, nk, tid);
            if (!next_self) stage_a_neigh(nxt, rowBase, nk, tid);
            asm volatile("cp.async.commit_group;" ::: "memory");
            if (next_self) lda_self(feat, rowBase, nk, tid, pf);
        }

        // ---- compute phase ph from cur ----
#pragma unroll
        for (int k16 = 0; k16 < 2; ++k16) {
            const uint32_t kb = k16 * 32 + lkp * 4;

            uint32_t a_hi[2][4], a_lo[2][4];
#pragma unroll
            for (int mt = 0; mt < 2; ++mt) {
                uint32_t rb = (wm * 32 + mt * 16 + lrow) * AST2 + kb;
                a_hi[mt][0] = *(const uint32_t*)(cur + AHI + rb);
                a_hi[mt][1] = *(const uint32_t*)(cur + AHI + rb + 8 * AST2);
                a_hi[mt][2] = *(const uint32_t*)(cur + AHI + rb + 16);
                a_hi[mt][3] = *(const uint32_t*)(cur + AHI + rb + 8 * AST2 + 16);
                a_lo[mt][0] = *(const uint32_t*)(cur + ALO + rb);
                a_lo[mt][1] = *(const uint32_t*)(cur + ALO + rb + 8 * AST2);
                a_lo[mt][2] = *(const uint32_t*)(cur + ALO + rb + 16);
                a_lo[mt][3] = *(const uint32_t*)(cur + ALO + rb + 8 * AST2 + 16);
            }

#pragma unroll
            for (int nt = 0; nt < 8; ++nt) {
                uint32_t nb = (wn * 64 + nt * 8 + lrow) * AST2 + kb;
                uint32_t b_hi[2], b_lo[2];
                b_hi[0] = *(const uint32_t*)(cur + WHI + nb);
                b_hi[1] = *(const uint32_t*)(cur + WHI + nb + 16);
                b_lo[0] = *(const uint32_t*)(cur + WLO + nb);
                b_lo[1] = *(const uint32_t*)(cur + WLO + nb + 16);
#pragma unroll
                for (int mt = 0; mt < 2; ++mt) {
                    mma16816(acc[mt][nt], a_hi[mt], b_hi);
                    mma16816(acc[mt][nt], a_hi[mt], b_lo);
                    mma16816(acc[mt][nt], a_lo[mt], b_hi);
                }
            }
        }

        if (have_next && next_self) sts_self(nxt, tid, pf);
    }

    // ---- epilogue: bias + store ----
    const float* bias = (const float*)smem;
#pragma unroll
    for (int mt = 0; mt < 2; ++mt) {
        int r0 = rowBase + wm * 32 + mt * 16 + lrow;
#pragma unroll
        for (int nt = 0; nt < 8; ++nt) {
            int col = wn * 64 + nt * 8 + lkp * 2;
            float b0 = bias[col], b1 = bias[col + 1];
            float2 v0 = make_float2(acc[mt][nt][0] + b0, acc[mt][nt][1] + b1);
            float2 v1 = make_float2(acc[mt][nt][2] + b0, acc[mt][nt][3] + b1);
            *(float2*)(out + (size_t)r0 * D + col)       = v0;
            *(float2*)(out + (size_t)(r0 + 8) * D + col) = v1;
        }
    }
}

// ============================================================
// launch
// ============================================================
extern "C" void kernel_launch(void* const* d_in, const int* in_sizes, int n_in,
                              void* d_out, int out_size) {
    const float* feat   = (const float*)d_in[0];
    const float* Wself  = (const float*)d_in[1];
    const float* bself  = (const float*)d_in[2];
    const float* Wneigh = (const float*)d_in[3];
    const float* bneigh = (const float*)d_in[4];
    const int*   src    = (const int*)d_in[5];
    const int*   dst    = (const int*)d_in[6];

    int n_edges = in_sizes[5];
    int n_dst   = out_size / D;

    static bool attr_done = false;
    if (!attr_done) {
        cudaFuncSetAttribute(gemm_pipe_kernel,
                             cudaFuncAttributeMaxDynamicSharedMemorySize, S_TOTAL);
        attr_done = true;
    }

    // 0) CSR offsets + W bf16 split/transpose + bias sum (fused)
    {
        int threads = 256;
        int offBlocks = (n_edges + 1 + threads - 1) / threads;
        prep_kernel<<<offBlocks + 16, threads>>>(dst, n_edges, n_dst,
                                                 Wself, Wneigh, bself, bneigh, offBlocks);
    }
    // 1) segment-mean aggregation -> bf16 hi/lo
    {
        int threads = 256;
        int blocks = (n_dst + 7) / 8;
        aggregate_kernel<<<blocks, threads>>>(feat, src, n_dst);
    }
    // 2) pipelined HMMA GEMM + bias (82 KB dynamic smem)
    {
        int blocks = n_dst / 128;   // 512
        gemm_pipe_kernel<<<blocks, 256, S_TOTAL>>>(feat, (float*)d_out);
    }
}